// round 4
// baseline (speedup 1.0000x reference)
#include <cuda_runtime.h>
#include <math.h>

#define N_    4096
#define B_    16
#define NT_   500
#define GRID_ 128
#define TPB_  512
#define NSLICE 16
#define KSL   256   // k per slice (NSLICE*KSL == N_)

// ---------------- persistent device state (allowed: __device__ globals) ----
__device__ float g_Wt[(size_t)N_ * N_];          // Wt[k*N_ + n] = W[n*N_ + k]   (64 MB)
__device__ float g_Yp[N_ * B_];                  // Yp[k*B_ + b]                 (256 KB)
__device__ float g_Zpart[NSLICE * B_ * N_];      // [slice][b][n]                (4 MB)
__device__ unsigned g_count = 0;
__device__ unsigned g_sense = 0;

typedef unsigned long long u64;

// ---------------- packed f32x2 helpers (Blackwell FFMA2: PTX-only) --------
__device__ __forceinline__ u64 pack2(float x) {
    u64 r; asm("mov.b64 %0, {%1, %1};" : "=l"(r) : "f"(x)); return r;
}
__device__ __forceinline__ void fma2(u64& d, u64 a, u64 b) {
    asm("fma.rn.f32x2 %0, %1, %2, %0;" : "+l"(d) : "l"(a), "l"(b));
}
// L2-only loads for cross-SM-mutated data (L1 not coherent within a
// persistent kernel -> .cg is load-bearing for correctness)
__device__ __forceinline__ float4 ldcg4(const float* p) {
    float4 v;
    asm("ld.global.cg.v4.f32 {%0,%1,%2,%3}, [%4];"
        : "=f"(v.x), "=f"(v.y), "=f"(v.z), "=f"(v.w) : "l"(p));
    return v;
}
__device__ __forceinline__ float ldcg(const float* p) {
    float v; asm("ld.global.cg.f32 %0, [%1];" : "=f"(v) : "l"(p)); return v;
}

// ---------------- grid-wide sense-reversing barrier -----------------------
// Total barriers per launch is EVEN, so g_sense/g_count return to (0,0)
// before the next graph replay (device globals persist across replays).
__device__ __forceinline__ void grid_barrier(unsigned& lsense) {
    __syncthreads();
    if (threadIdx.x == 0) {
        unsigned s = lsense ^ 1u;
        __threadfence();
        if (atomicAdd(&g_count, 1u) == GRID_ - 1u) {
            atomicExch(&g_count, 0u);
            __threadfence();
            atomicExch(&g_sense, s);
        } else {
            volatile unsigned* gs = &g_sense;
            while (*gs != s) { }
            __threadfence();
        }
        lsense = s;
    }
    __syncthreads();
}

// ---------------- main persistent kernel ----------------------------------
__global__ void __launch_bounds__(TPB_, 1)
snn_kernel(const float* __restrict__ W, const float* __restrict__ x0,
           const float* __restrict__ V0, const float* __restrict__ Y0,
           float* __restrict__ out)
{
    // Y staged in smem: 2 slices x 256 k x 16 b  (32 KB)
    __shared__ float Ys[2 * KSL * B_];
    __shared__ float tile[32][33];

    const int g = blockIdx.x;
    const int t = threadIdx.x;
    unsigned lsense = 0;

    // ---- init A: tiled transpose W -> g_Wt (coalesced both sides) ----
    {
        const int TPR = N_ / 32;            // 128 tiles per side
        const int i = t >> 5, j = t & 31;   // 16 rows x 32 cols per pass
        for (int tt = g; tt < TPR * TPR; tt += GRID_) {
            const int trow = tt / TPR;      // n-block
            const int tcol = tt % TPR;      // k-block
            #pragma unroll
            for (int r = 0; r < 32; r += 16)
                tile[r + i][j] = W[(size_t)(trow * 32 + r + i) * N_ + tcol * 32 + j];
            __syncthreads();
            #pragma unroll
            for (int r = 0; r < 32; r += 16)
                g_Wt[(size_t)(tcol * 32 + r + i) * N_ + trow * 32 + j] = tile[j][r + i];
            __syncthreads();
        }
    }

    // ---- init B: pack Y0 -> Yp[k][b]  (65536 = GRID_*TPB_ exactly) ----
    {
        const int m = g * TPB_ + t;
        const int k = m >> 4, b = m & 15;
        g_Yp[m] = Y0[b * N_ + k];
    }

    // ---- per-thread neuron state (1 item/thread), registers for 500 steps
    const int u  = g * TPB_ + t;            // 0..65535
    const int nn = u & (N_ - 1);            // neuron index
    const int bb = u >> 12;                 // batch index
    float Vr = V0[bb * N_ + nn];
    float Yr = Y0[bb * N_ + nn];
    const float xr = x0[bb * N_ + nn];
    float Rr = 0.0f;

    // ---- GEMM task mapping ----
    // g: nt = g>>3 (16 n-tiles of 256), sp = g&7 (slice pair {2sp, 2sp+1})
    // t: h = t>>8 (slice in pair), bg = t&7 (batch pair), no8 = (t>>3)&31
    const int nt  = g >> 3;
    const int sp  = g & 7;
    const int h   = t >> 8;
    const int bg  = t & 7;
    const int no8 = (t >> 3) & 31;
    const int n0  = nt * 256 + no8 * 8;     // this thread's 8-n group
    const int sl  = 2 * sp + h;             // k-slice 0..15
    const float* wt_base = g_Wt + (size_t)sl * KSL * N_ + n0;
    const float* yg      = g_Yp + 2 * sp * KSL * B_;   // 32 KB (2 slices)
    const float* ysm     = Ys + h * (KSL * B_) + 2 * bg;
    float* z0 = g_Zpart + ((size_t)sl * B_ + 2 * bg) * N_ + n0;  // row b=2bg
    float* z1 = z0 + N_;                                          // row b=2bg+1

    grid_barrier(lsense);                        // barrier 1: init done

    const float cY    = (float)(0.1 / 8.0);         // dt / tausyn
    const float scale = (float)(0.1 / (500 * 0.1)); // dt / T

    for (int step = 0; step < NT_; ++step) {
        // ---- stage this block's 2 Y slices into smem (coalesced, L2 reads)
        #pragma unroll
        for (int i = 0; i < (2 * KSL * B_) / (4 * TPB_); ++i) {  // 4 float4/thr
            const int idx = (i * TPB_ + t) * 4;
            const float4 v = ldcg4(yg + idx);
            *reinterpret_cast<float4*>(&Ys[idx]) = v;
        }
        __syncthreads();

        // ======== phase 1: partial GEMM (8 n x 2 b, 256 k) ====
        u64 A00 = 0, A01 = 0, A02 = 0, A03 = 0;   // b = 2bg
        u64 A10 = 0, A11 = 0, A12 = 0, A13 = 0;   // b = 2bg+1
        #pragma unroll 8
        for (int kk = 0; kk < KSL; ++kk) {
            // W: 8 contiguous floats = 4 native f32x2 pairs (no packing)
            const ulonglong2 wv0 =
                *reinterpret_cast<const ulonglong2*>(wt_base + (size_t)kk * N_);
            const ulonglong2 wv1 =
                *reinterpret_cast<const ulonglong2*>(wt_base + (size_t)kk * N_ + 4);
            // Y: this thread's 2 batches (64B warp footprint, conflict-free)
            const float2 y2 = *reinterpret_cast<const float2*>(ysm + kk * B_);
            const u64 yp0 = pack2(y2.x);
            const u64 yp1 = pack2(y2.y);
            fma2(A00, wv0.x, yp0); fma2(A01, wv0.y, yp0);
            fma2(A02, wv1.x, yp0); fma2(A03, wv1.y, yp0);
            fma2(A10, wv0.x, yp1); fma2(A11, wv0.y, yp1);
            fma2(A12, wv1.x, yp1); fma2(A13, wv1.y, yp1);
        }
        // store 16 partials: 2 rows x 2 STG.128, fully coalesced in n
        {
            union F2 { u64 u; float2 f; };
            F2 a{A00}, b{A01}, c{A02}, d{A03};
            reinterpret_cast<float4*>(z0)[0] = make_float4(a.f.x, a.f.y, b.f.x, b.f.y);
            reinterpret_cast<float4*>(z0)[1] = make_float4(c.f.x, c.f.y, d.f.x, d.f.y);
            F2 e{A10}, f{A11}, gg{A12}, hh{A13};
            reinterpret_cast<float4*>(z1)[0] = make_float4(e.f.x, e.f.y, f.f.x, f.f.y);
            reinterpret_cast<float4*>(z1)[1] = make_float4(gg.f.x, gg.f.y, hh.f.x, hh.f.y);
        }

        grid_barrier(lsense);                    // partials visible

        // ======== phase 2: neuron update (1 item, state in registers) ====
        {
            float Z = xr;
            #pragma unroll
            for (int s2 = 0; s2 < NSLICE; ++s2)
                Z += ldcg(g_Zpart + ((size_t)s2 * B_ + bb) * N_ + nn);
            float num = -(Vr - (-72.0f));
            num = num + expf(Vr - (-55.0f));
            num = num + Z;
            const float dV = num / 10.0f;
            float Vn = Vr + 0.1f * dV;
            Vn = fmaxf(Vn, -85.0f);
            const bool sp2 = (Vn >= 0.0f);
            const float S = sp2 ? 10.0f : 0.0f;
            if (sp2) Vn = -72.0f;
            Vr = Vn;
            Yr = Yr + cY * (S - Yr);
            Rr += S;
            g_Yp[nn * B_ + bb] = Yr;
        }

        grid_barrier(lsense);                    // Yp visible for next step
    }

    // ---- output: r * dt/T  (layout out[b][n], coalesced) ----
    out[bb * N_ + nn] = Rr * scale;

    grid_barrier(lsense);  // pad: total = 1 + 2*NT_ + 1 = 1002 (even)
}

extern "C" void kernel_launch(void* const* d_in, const int* in_sizes, int n_in,
                              void* d_out, int out_size)
{
    (void)in_sizes; (void)n_in; (void)out_size;
    const float* W  = (const float*)d_in[0];
    const float* x0 = (const float*)d_in[1];
    const float* V0 = (const float*)d_in[2];
    const float* Y0 = (const float*)d_in[3];
    snn_kernel<<<GRID_, TPB_>>>(W, x0, V0, Y0, (float*)d_out);
}

// round 5
// speedup vs baseline: 1.5337x; 1.5337x over previous
#include <cuda_runtime.h>
#include <math.h>

#define N_    4096
#define B_    16
#define NT_   500
#define GRID_ 128
#define TPB_  512
#define NSLICE 32
#define KSL   128   // k per slice (NSLICE*KSL == N_)

// ---------------- persistent device state (allowed: __device__ globals) ----
__device__ float g_Wt[(size_t)N_ * N_];          // Wt[k*N_ + n] = W[n*N_ + k]   (64 MB)
__device__ float g_Yp[N_ * B_];                  // Yp[k*B_ + b]                 (256 KB)
__device__ float g_Zpart[(size_t)NSLICE * B_ * N_]; // [slice][b][n]             (8 MB)
__device__ unsigned g_count = 0;
__device__ unsigned g_sense = 0;

typedef unsigned long long u64;

// ---------------- packed f32x2 helpers (Blackwell FFMA2: PTX-only) --------
__device__ __forceinline__ u64 pack2(float x) {
    u64 r; asm("mov.b64 %0, {%1, %1};" : "=l"(r) : "f"(x)); return r;
}
__device__ __forceinline__ void fma2(u64& d, u64 a, u64 b) {
    asm("fma.rn.f32x2 %0, %1, %2, %0;" : "+l"(d) : "l"(a), "l"(b));
}
// L2-only loads for cross-SM-mutated data (L1 not coherent within a
// persistent kernel -> .cg is load-bearing for correctness)
__device__ __forceinline__ float4 ldcg4(const float* p) {
    float4 v;
    asm("ld.global.cg.v4.f32 {%0,%1,%2,%3}, [%4];"
        : "=f"(v.x), "=f"(v.y), "=f"(v.z), "=f"(v.w) : "l"(p));
    return v;
}
__device__ __forceinline__ float ldcg(const float* p) {
    float v; asm("ld.global.cg.f32 %0, [%1];" : "=f"(v) : "l"(p)); return v;
}

// ---------------- grid-wide sense-reversing barrier -----------------------
// Total barriers per launch is EVEN, so g_sense/g_count return to (0,0)
// before the next graph replay (device globals persist across replays).
__device__ __forceinline__ void grid_barrier(unsigned& lsense) {
    __syncthreads();
    if (threadIdx.x == 0) {
        unsigned s = lsense ^ 1u;
        __threadfence();
        if (atomicAdd(&g_count, 1u) == GRID_ - 1u) {
            atomicExch(&g_count, 0u);
            __threadfence();
            atomicExch(&g_sense, s);
        } else {
            volatile unsigned* gs = &g_sense;
            while (*gs != s) { }
            __threadfence();
        }
        lsense = s;
    }
    __syncthreads();
}

// ---------------- main persistent kernel ----------------------------------
__global__ void __launch_bounds__(TPB_, 1)
snn_kernel(const float* __restrict__ W, const float* __restrict__ x0,
           const float* __restrict__ V0, const float* __restrict__ Y0,
           float* __restrict__ out)
{
    // Y staged in smem: 2 slices x 128 k x 16 b  (16 KB)
    __shared__ float Ys[2 * KSL * B_];
    __shared__ float tile[32][33];

    const int g = blockIdx.x;
    const int t = threadIdx.x;
    unsigned lsense = 0;

    // ---- init A: tiled transpose W -> g_Wt (coalesced both sides) ----
    {
        const int TPR = N_ / 32;            // 128 tiles per side
        const int i = t >> 5, j = t & 31;   // 16 rows x 32 cols per pass
        for (int tt = g; tt < TPR * TPR; tt += GRID_) {
            const int trow = tt / TPR;      // n-block
            const int tcol = tt % TPR;      // k-block
            #pragma unroll
            for (int r = 0; r < 32; r += 16)
                tile[r + i][j] = W[(size_t)(trow * 32 + r + i) * N_ + tcol * 32 + j];
            __syncthreads();
            #pragma unroll
            for (int r = 0; r < 32; r += 16)
                g_Wt[(size_t)(tcol * 32 + r + i) * N_ + trow * 32 + j] = tile[j][r + i];
            __syncthreads();
        }
    }

    // ---- init B: pack Y0 -> Yp[k][b]  (65536 = GRID_*TPB_ exactly) ----
    {
        const int m = g * TPB_ + t;
        const int k = m >> 4, b = m & 15;
        g_Yp[m] = Y0[b * N_ + k];
    }

    // ---- per-thread neuron state (1 item/thread), registers for 500 steps
    const int u  = g * TPB_ + t;            // 0..65535
    const int nn = u & (N_ - 1);            // neuron index
    const int bb = u >> 12;                 // batch index
    float Vr = V0[bb * N_ + nn];
    float Yr = Y0[bb * N_ + nn];
    const float xr = x0[bb * N_ + nn];
    float Rr = 0.0f;

    // ---- GEMM task mapping ----
    // g: nt = g>>4 (8 n-tiles of 512 n), sg = g&15 (slice pair {2sg,2sg+1})
    // t: ng = t&255 (n pair within tile), h = t>>8 (slice in pair)
    const int nt = g >> 4;
    const int sg = g & 15;
    const int ng = t & 255;
    const int h  = t >> 8;
    const int n0 = nt * 512 + ng * 2;       // this thread's n pair
    const int sl = 2 * sg + h;              // k-slice 0..31
    const float* wt_base = g_Wt + (size_t)sl * KSL * N_ + n0;
    const float* yg      = g_Yp + 2 * sg * KSL * B_;   // 16 KB (2 slices)
    const float* ysm     = Ys + h * (KSL * B_);
    float* zbase = g_Zpart + (size_t)sl * B_ * N_ + n0;

    grid_barrier(lsense);                        // barrier 1: init done

    const float cY    = (float)(0.1 / 8.0);         // dt / tausyn
    const float scale = (float)(0.1 / (500 * 0.1)); // dt / T

    for (int step = 0; step < NT_; ++step) {
        // ---- stage this block's 2 Y slices into smem (coalesced, L2 reads)
        #pragma unroll
        for (int i = 0; i < (2 * KSL * B_) / (4 * TPB_); ++i) {  // 2 float4/thr
            const int idx = (i * TPB_ + t) * 4;
            const float4 v = ldcg4(yg + idx);
            *reinterpret_cast<float4*>(&Ys[idx]) = v;
        }
        __syncthreads();

        // ======== phase 1: partial GEMM (2 n x 16 b, 128 k) ====
        // Accumulators paired over BATCHES: A0[j]=(Z[2j][n0],Z[2j+1][n0]),
        //                                   A1[j]=(Z[2j][n1],Z[2j+1][n1])
        u64 A0[8], A1[8];
        #pragma unroll
        for (int j = 0; j < 8; ++j) { A0[j] = 0ull; A1[j] = 0ull; }

        #pragma unroll 8
        for (int kk = 0; kk < KSL; ++kk) {
            // W: 2 floats, warp spans 256B contiguous
            const float2 w2 = *reinterpret_cast<const float2*>(wt_base + (size_t)kk * N_);
            const u64 wp0 = pack2(w2.x);
            const u64 wp1 = pack2(w2.y);
            // Y row: 16 b as 8 native u64 pairs, same addr across warp (bcast)
            const ulonglong2* yrow = reinterpret_cast<const ulonglong2*>(ysm + kk * B_);
            const ulonglong2 p0 = yrow[0];
            const ulonglong2 p1 = yrow[1];
            const ulonglong2 p2 = yrow[2];
            const ulonglong2 p3 = yrow[3];
            fma2(A0[0], wp0, p0.x); fma2(A1[0], wp1, p0.x);
            fma2(A0[1], wp0, p0.y); fma2(A1[1], wp1, p0.y);
            fma2(A0[2], wp0, p1.x); fma2(A1[2], wp1, p1.x);
            fma2(A0[3], wp0, p1.y); fma2(A1[3], wp1, p1.y);
            fma2(A0[4], wp0, p2.x); fma2(A1[4], wp1, p2.x);
            fma2(A0[5], wp0, p2.y); fma2(A1[5], wp1, p2.y);
            fma2(A0[6], wp0, p3.x); fma2(A1[6], wp1, p3.x);
            fma2(A0[7], wp0, p3.y); fma2(A1[7], wp1, p3.y);
        }
        // store partials: Zpart[sl][b][n0..n1], 16 coalesced STG.64
        {
            union F2 { u64 u; float2 f; };
            #pragma unroll
            for (int j = 0; j < 8; ++j) {
                F2 a{A0[j]}, b{A1[j]};
                // b = 2j   row: (Z[2j][n0],   Z[2j][n1])
                *reinterpret_cast<float2*>(zbase + (size_t)(2 * j) * N_) =
                    make_float2(a.f.x, b.f.x);
                // b = 2j+1 row: (Z[2j+1][n0], Z[2j+1][n1])
                *reinterpret_cast<float2*>(zbase + (size_t)(2 * j + 1) * N_) =
                    make_float2(a.f.y, b.f.y);
            }
        }

        grid_barrier(lsense);                    // partials visible

        // ======== phase 2: neuron update (1 item, state in registers) ====
        {
            float Z = xr;
            #pragma unroll
            for (int s2 = 0; s2 < NSLICE; ++s2)
                Z += ldcg(g_Zpart + ((size_t)s2 * B_ + bb) * N_ + nn);
            float num = -(Vr - (-72.0f));
            num = num + expf(Vr - (-55.0f));
            num = num + Z;
            const float dV = num / 10.0f;
            float Vn = Vr + 0.1f * dV;
            Vn = fmaxf(Vn, -85.0f);
            const bool sp2 = (Vn >= 0.0f);
            const float S = sp2 ? 10.0f : 0.0f;
            if (sp2) Vn = -72.0f;
            Vr = Vn;
            Yr = Yr + cY * (S - Yr);
            Rr += S;
            g_Yp[nn * B_ + bb] = Yr;
        }

        grid_barrier(lsense);                    // Yp visible for next step
    }

    // ---- output: r * dt/T  (layout out[b][n], coalesced) ----
    out[bb * N_ + nn] = Rr * scale;

    grid_barrier(lsense);  // pad: total = 1 + 2*NT_ + 1 = 1002 (even)
}

extern "C" void kernel_launch(void* const* d_in, const int* in_sizes, int n_in,
                              void* d_out, int out_size)
{
    (void)in_sizes; (void)n_in; (void)out_size;
    const float* W  = (const float*)d_in[0];
    const float* x0 = (const float*)d_in[1];
    const float* V0 = (const float*)d_in[2];
    const float* Y0 = (const float*)d_in[3];
    snn_kernel<<<GRID_, TPB_>>>(W, x0, V0, Y0, (float*)d_out);
}

// round 6
// speedup vs baseline: 189.9784x; 123.8662x over previous
#include <cuda_runtime.h>
#include <math.h>

#define N_    4096
#define B_    16
#define NT_   500
#define GRID_ 128
#define TPB_  512
#define NSLICE 32
#define KSL   128   // k per slice (NSLICE*KSL == N_)

// ---------------- persistent device state (allowed: __device__ globals) ----
__device__ float g_Wt[(size_t)N_ * N_];          // Wt[k*N_ + n] = W[n*N_ + k]   (64 MB)
__device__ float g_Yp[N_ * B_];                  // Yp[k*B_ + b]                 (256 KB)
__device__ float g_Zpart[(size_t)NSLICE * B_ * N_]; // [slice][b][n]             (8 MB)
__device__ unsigned g_count = 0;
__device__ unsigned g_sense = 0;
__device__ unsigned g_anyspike = 0;              // set if any spike can occur

typedef unsigned long long u64;

// ---------------- packed f32x2 helpers (Blackwell FFMA2: PTX-only) --------
__device__ __forceinline__ u64 pack2(float x) {
    u64 r; asm("mov.b64 %0, {%1, %1};" : "=l"(r) : "f"(x)); return r;
}
__device__ __forceinline__ void fma2(u64& d, u64 a, u64 b) {
    asm("fma.rn.f32x2 %0, %1, %2, %0;" : "+l"(d) : "l"(a), "l"(b));
}
// L2-only loads for cross-SM-mutated data (L1 not coherent within a
// persistent kernel -> .cg is load-bearing for correctness)
__device__ __forceinline__ float4 ldcg4(const float* p) {
    float4 v;
    asm("ld.global.cg.v4.f32 {%0,%1,%2,%3}, [%4];"
        : "=f"(v.x), "=f"(v.y), "=f"(v.z), "=f"(v.w) : "l"(p));
    return v;
}
__device__ __forceinline__ float ldcg(const float* p) {
    float v; asm("ld.global.cg.f32 %0, [%1];" : "=f"(v) : "l"(p)); return v;
}
__device__ __forceinline__ unsigned ldcgu(const unsigned* p) {
    unsigned v; asm("ld.global.cg.u32 %0, [%1];" : "=r"(v) : "l"(p)); return v;
}

// ---------------- grid-wide sense-reversing barrier -----------------------
__device__ __forceinline__ void grid_barrier(unsigned& lsense) {
    __syncthreads();
    if (threadIdx.x == 0) {
        unsigned s = lsense ^ 1u;
        __threadfence();
        if (atomicAdd(&g_count, 1u) == GRID_ - 1u) {
            atomicExch(&g_count, 0u);
            __threadfence();
            atomicExch(&g_sense, s);
        } else {
            volatile unsigned* gs = &g_sense;
            while (*gs != s) { }
            __threadfence();
        }
        lsense = s;
    }
    __syncthreads();
}

// ================= kernel 0: reset spike flag ==============================
__global__ void reset_flag_kernel() {
    if (threadIdx.x == 0 && blockIdx.x == 0) g_anyspike = 0u;
}

// ================= kernel 1: spike-possibility checker =====================
// Simulates each neuron's EXACT reference trajectory under the hypothesis
// Y == 0 (=> Z = x0, constant). If no neuron ever spikes under this
// hypothesis, then by induction the hypothesis is the true trajectory
// (no spikes -> S=0 -> Y stays exactly 0 -> Z stays exactly x0).
// If ANY spike occurs, sets g_anyspike and the full simulator runs.
__global__ void __launch_bounds__(TPB_, 1)
check_kernel(const float* __restrict__ x0, const float* __restrict__ V0)
{
    const int u  = blockIdx.x * TPB_ + threadIdx.x;   // 0..65535
    const int nn = u & (N_ - 1);
    const int bb = u >> 12;
    float V = V0[bb * N_ + nn];
    const float Z = x0[bb * N_ + nn];

    bool spiked = false;
    #pragma unroll 4
    for (int step = 0; step < NT_; ++step) {
        float num = -(V - (-72.0f));
        num = num + expf(V - (-55.0f));
        num = num + Z;
        const float dV = num / 10.0f;
        float Vn = V + 0.1f * dV;
        Vn = fmaxf(Vn, -85.0f);
        if (Vn >= 0.0f) { spiked = true; break; }
        V = Vn;
    }
    if (__any_sync(0xFFFFFFFFu, spiked)) {
        if ((threadIdx.x & 31) == 0) atomicOr(&g_anyspike, 1u);
    }
}

// ================= kernel 2: gated full simulator ==========================
// Fast path (g_anyspike == 0): output is exactly zero (proved by checker);
// every thread writes its one element and exits before any barrier.
// Slow path: full dense fp32 simulation (verified in rounds 1-5).
__global__ void __launch_bounds__(TPB_, 1)
snn_kernel(const float* __restrict__ W, const float* __restrict__ x0,
           const float* __restrict__ V0, const float* __restrict__ Y0,
           float* __restrict__ out)
{
    // Y staged in smem: 2 slices x 128 k x 16 b  (16 KB)
    __shared__ float Ys[2 * KSL * B_];
    __shared__ float tile[32][33];

    const int g = blockIdx.x;
    const int t = threadIdx.x;
    unsigned lsense = 0;

    // ---- per-thread neuron identity ----
    const int u  = g * TPB_ + t;            // 0..65535
    const int nn = u & (N_ - 1);            // neuron index
    const int bb = u >> 12;                 // batch index

    // ---- gate: if no spike is possible, r == 0 exactly ----
    if (ldcgu(&g_anyspike) == 0u) {
        out[bb * N_ + nn] = 0.0f;           // covers out exactly (65536 elts)
        return;                              // uniform exit: no barriers touched
    }

    // =================== full dense simulation (fallback) ==================

    // ---- init A: tiled transpose W -> g_Wt (coalesced both sides) ----
    {
        const int TPR = N_ / 32;            // 128 tiles per side
        const int i = t >> 5, j = t & 31;   // 16 rows x 32 cols per pass
        for (int tt = g; tt < TPR * TPR; tt += GRID_) {
            const int trow = tt / TPR;      // n-block
            const int tcol = tt % TPR;      // k-block
            #pragma unroll
            for (int r = 0; r < 32; r += 16)
                tile[r + i][j] = W[(size_t)(trow * 32 + r + i) * N_ + tcol * 32 + j];
            __syncthreads();
            #pragma unroll
            for (int r = 0; r < 32; r += 16)
                g_Wt[(size_t)(tcol * 32 + r + i) * N_ + trow * 32 + j] = tile[j][r + i];
            __syncthreads();
        }
    }

    // ---- init B: pack Y0 -> Yp[k][b]  (65536 = GRID_*TPB_ exactly) ----
    {
        const int m = g * TPB_ + t;
        const int k = m >> 4, b = m & 15;
        g_Yp[m] = Y0[b * N_ + k];
    }

    // ---- per-thread neuron state, registers for 500 steps ----
    float Vr = V0[bb * N_ + nn];
    float Yr = Y0[bb * N_ + nn];
    const float xr = x0[bb * N_ + nn];
    float Rr = 0.0f;

    // ---- GEMM task mapping ----
    const int nt = g >> 4;
    const int sg = g & 15;
    const int ng = t & 255;
    const int h  = t >> 8;
    const int n0 = nt * 512 + ng * 2;       // this thread's n pair
    const int sl = 2 * sg + h;              // k-slice 0..31
    const float* wt_base = g_Wt + (size_t)sl * KSL * N_ + n0;
    const float* yg      = g_Yp + 2 * sg * KSL * B_;   // 16 KB (2 slices)
    const float* ysm     = Ys + h * (KSL * B_);
    float* zbase = g_Zpart + (size_t)sl * B_ * N_ + n0;

    grid_barrier(lsense);                        // barrier 1: init done

    const float cY    = (float)(0.1 / 8.0);         // dt / tausyn
    const float scale = (float)(0.1 / (500 * 0.1)); // dt / T

    for (int step = 0; step < NT_; ++step) {
        // ---- stage this block's 2 Y slices into smem (coalesced, L2 reads)
        #pragma unroll
        for (int i = 0; i < (2 * KSL * B_) / (4 * TPB_); ++i) {  // 2 float4/thr
            const int idx = (i * TPB_ + t) * 4;
            const float4 v = ldcg4(yg + idx);
            *reinterpret_cast<float4*>(&Ys[idx]) = v;
        }
        __syncthreads();

        // ======== phase 1: partial GEMM (2 n x 16 b, 128 k) ====
        u64 A0[8], A1[8];
        #pragma unroll
        for (int j = 0; j < 8; ++j) { A0[j] = 0ull; A1[j] = 0ull; }

        #pragma unroll 8
        for (int kk = 0; kk < KSL; ++kk) {
            const float2 w2 = *reinterpret_cast<const float2*>(wt_base + (size_t)kk * N_);
            const u64 wp0 = pack2(w2.x);
            const u64 wp1 = pack2(w2.y);
            const ulonglong2* yrow = reinterpret_cast<const ulonglong2*>(ysm + kk * B_);
            const ulonglong2 p0 = yrow[0];
            const ulonglong2 p1 = yrow[1];
            const ulonglong2 p2 = yrow[2];
            const ulonglong2 p3 = yrow[3];
            fma2(A0[0], wp0, p0.x); fma2(A1[0], wp1, p0.x);
            fma2(A0[1], wp0, p0.y); fma2(A1[1], wp1, p0.y);
            fma2(A0[2], wp0, p1.x); fma2(A1[2], wp1, p1.x);
            fma2(A0[3], wp0, p1.y); fma2(A1[3], wp1, p1.y);
            fma2(A0[4], wp0, p2.x); fma2(A1[4], wp1, p2.x);
            fma2(A0[5], wp0, p2.y); fma2(A1[5], wp1, p2.y);
            fma2(A0[6], wp0, p3.x); fma2(A1[6], wp1, p3.x);
            fma2(A0[7], wp0, p3.y); fma2(A1[7], wp1, p3.y);
        }
        // store partials: Zpart[sl][b][n0..n1], 16 coalesced STG.64
        {
            union F2 { u64 u; float2 f; };
            #pragma unroll
            for (int j = 0; j < 8; ++j) {
                F2 a{A0[j]}, b{A1[j]};
                *reinterpret_cast<float2*>(zbase + (size_t)(2 * j) * N_) =
                    make_float2(a.f.x, b.f.x);
                *reinterpret_cast<float2*>(zbase + (size_t)(2 * j + 1) * N_) =
                    make_float2(a.f.y, b.f.y);
            }
        }

        grid_barrier(lsense);                    // partials visible

        // ======== phase 2: neuron update (1 item, state in registers) ====
        {
            float Z = xr;
            #pragma unroll
            for (int s2 = 0; s2 < NSLICE; ++s2)
                Z += ldcg(g_Zpart + ((size_t)s2 * B_ + bb) * N_ + nn);
            float num = -(Vr - (-72.0f));
            num = num + expf(Vr - (-55.0f));
            num = num + Z;
            const float dV = num / 10.0f;
            float Vn = Vr + 0.1f * dV;
            Vn = fmaxf(Vn, -85.0f);
            const bool sp2 = (Vn >= 0.0f);
            const float S = sp2 ? 10.0f : 0.0f;
            if (sp2) Vn = -72.0f;
            Vr = Vn;
            Yr = Yr + cY * (S - Yr);
            Rr += S;
            g_Yp[nn * B_ + bb] = Yr;
        }

        grid_barrier(lsense);                    // Yp visible for next step
    }

    // ---- output: r * dt/T  (layout out[b][n], coalesced) ----
    out[bb * N_ + nn] = Rr * scale;

    grid_barrier(lsense);  // pad: total = 1 + 2*NT_ + 1 = 1002 (even)
}

extern "C" void kernel_launch(void* const* d_in, const int* in_sizes, int n_in,
                              void* d_out, int out_size)
{
    (void)in_sizes; (void)n_in; (void)out_size;
    const float* W  = (const float*)d_in[0];
    const float* x0 = (const float*)d_in[1];
    const float* V0 = (const float*)d_in[2];
    const float* Y0 = (const float*)d_in[3];
    reset_flag_kernel<<<1, 32>>>();
    check_kernel<<<GRID_, TPB_>>>(x0, V0);
    snn_kernel<<<GRID_, TPB_>>>(W, x0, V0, Y0, (float*)d_out);
}

// round 7
// speedup vs baseline: 1257.6345x; 6.6199x over previous
#include <cuda_runtime.h>
#include <math.h>

#define N_    4096
#define B_    16
#define NT_   500
#define GRID_ 128
#define TPB_  512
#define NSLICE 32
#define KSL   128   // k per slice (NSLICE*KSL == N_)

// ---------------- persistent device state (allowed: __device__ globals) ----
__device__ float g_Wt[(size_t)N_ * N_];          // Wt[k*N_ + n] = W[n*N_ + k]   (64 MB)
__device__ float g_Yp[N_ * B_];                  // Yp[k*B_ + b]                 (256 KB)
__device__ float g_Zpart[(size_t)NSLICE * B_ * N_]; // [slice][b][n]             (8 MB)
__device__ unsigned g_count = 0;
__device__ unsigned g_sense = 0;
__device__ unsigned g_anyspike = 0;              // set if any spike can occur

typedef unsigned long long u64;

// ---------------- packed f32x2 helpers (Blackwell FFMA2: PTX-only) --------
__device__ __forceinline__ u64 pack2(float x) {
    u64 r; asm("mov.b64 %0, {%1, %1};" : "=l"(r) : "f"(x)); return r;
}
__device__ __forceinline__ void fma2(u64& d, u64 a, u64 b) {
    asm("fma.rn.f32x2 %0, %1, %2, %0;" : "+l"(d) : "l"(a), "l"(b));
}
// L2-only loads for cross-SM-mutated data (L1 not coherent within a
// persistent kernel -> .cg is load-bearing for correctness)
__device__ __forceinline__ float4 ldcg4(const float* p) {
    float4 v;
    asm("ld.global.cg.v4.f32 {%0,%1,%2,%3}, [%4];"
        : "=f"(v.x), "=f"(v.y), "=f"(v.z), "=f"(v.w) : "l"(p));
    return v;
}
__device__ __forceinline__ float ldcg(const float* p) {
    float v; asm("ld.global.cg.f32 %0, [%1];" : "=f"(v) : "l"(p)); return v;
}
__device__ __forceinline__ unsigned ldcgu(const unsigned* p) {
    unsigned v; asm("ld.global.cg.u32 %0, [%1];" : "=r"(v) : "l"(p)); return v;
}

// ---------------- grid-wide sense-reversing barrier -----------------------
// Total barrier count per launch is EVEN on every path, so g_sense/g_count
// return to (0,0) before the next graph replay.
__device__ __forceinline__ void grid_barrier(unsigned& lsense) {
    __syncthreads();
    if (threadIdx.x == 0) {
        unsigned s = lsense ^ 1u;
        __threadfence();
        if (atomicAdd(&g_count, 1u) == GRID_ - 1u) {
            atomicExch(&g_count, 0u);
            __threadfence();
            atomicExch(&g_sense, s);
        } else {
            volatile unsigned* gs = &g_sense;
            while (*gs != s) { }
            __threadfence();
        }
        lsense = s;
    }
    __syncthreads();
}

// ================= single fused kernel =====================================
// Phase 0 (O(1) analytic spike test): the Euler map g(V)=V+0.1*f(V) with
//   f(V) = (-(V-EL) + e^{V-VT} + Z)/tau  is strictly monotone increasing
// (g' = 0.99 + 0.01*e^{V+55} > 0), so iterates can NEVER cross a fixed point
// (a root of f). With Y0 == 0, Z = x0 is constant, hence per neuron:
//   - if f(V0) <= 0:  V decreases monotonically -> no spike, ever.
//   - if f(V0) > 0:   V rises; a spike requires NO root of f in (V0, VTH),
//     i.e. Z > max h(V) over [V0,VTH) where h(V)=V-EL-e^{V-VT}, max = 16
//     (attained at V = VT = -55). If Z <= 16, the first root above V0 is an
//     attracting barrier -> no spike (rounding-robust: crossing it by 1 ulp
//     lands in f<0 territory and is pushed back).
// And no spikes -> S == 0 -> Y stays exactly 0 -> Z stays exactly x0
// (induction), so the hypothesis is self-validating and r == 0 exactly.
// Safety margins 0.01 / 0.5 absorb fp32 evaluation error; any violation
// (including Y0 != 0) falls back to the full dense simulation.
__global__ void __launch_bounds__(TPB_, 1)
snn_kernel(const float* __restrict__ W, const float* __restrict__ x0,
           const float* __restrict__ V0, const float* __restrict__ Y0,
           float* __restrict__ out)
{
    // Y staged in smem: 2 slices x 128 k x 16 b  (16 KB)
    __shared__ float Ys[2 * KSL * B_];
    __shared__ float tile[32][33];

    const int g = blockIdx.x;
    const int t = threadIdx.x;
    unsigned lsense = 0;

    // ---- per-thread neuron identity (u is also the linear [b][n] index) --
    const int u  = g * TPB_ + t;            // 0..65535
    const int nn = u & (N_ - 1);            // neuron index
    const int bb = u >> 12;                 // batch index

    // ================= phase 0: analytic spike-possibility check ==========
    {
        const float yv = Y0[u];
        const float xv = x0[u];
        const float Vv = V0[u];
        const float h0 = Vv + 72.0f - expf(Vv + 55.0f);   // h(V0)
        const bool safe =
            (yv == 0.0f) &&
            ((xv <= h0 - 0.01f) ||                 // f(V0) < 0: monotone decay
             (Vv <= -55.0f && xv <= 15.5f));       // barrier root exists below VT
        if (__any_sync(0xFFFFFFFFu, !safe)) {
            if ((t & 31) == 0) atomicOr(&g_anyspike, 1u);
        }
    }
    grid_barrier(lsense);                        // barrier A

    if (ldcgu(&g_anyspike) == 0u) {
        out[u] = 0.0f;                           // r == 0 exactly (proved)
        grid_barrier(lsense);                    // barrier B: total 2 (even)
        return;
    }

    // =================== full dense simulation (fallback) ==================

    // ---- init A: tiled transpose W -> g_Wt (coalesced both sides) ----
    {
        const int TPR = N_ / 32;            // 128 tiles per side
        const int i = t >> 5, j = t & 31;   // 16 rows x 32 cols per pass
        for (int tt = g; tt < TPR * TPR; tt += GRID_) {
            const int trow = tt / TPR;      // n-block
            const int tcol = tt % TPR;      // k-block
            #pragma unroll
            for (int r = 0; r < 32; r += 16)
                tile[r + i][j] = W[(size_t)(trow * 32 + r + i) * N_ + tcol * 32 + j];
            __syncthreads();
            #pragma unroll
            for (int r = 0; r < 32; r += 16)
                g_Wt[(size_t)(tcol * 32 + r + i) * N_ + trow * 32 + j] = tile[j][r + i];
            __syncthreads();
        }
    }

    // ---- init B: pack Y0 -> Yp[k][b]  (65536 = GRID_*TPB_ exactly) ----
    {
        const int m = g * TPB_ + t;
        const int k = m >> 4, b = m & 15;
        g_Yp[m] = Y0[b * N_ + k];
    }

    // ---- per-thread neuron state, registers for 500 steps ----
    float Vr = V0[bb * N_ + nn];
    float Yr = Y0[bb * N_ + nn];
    const float xr = x0[bb * N_ + nn];
    float Rr = 0.0f;

    // ---- GEMM task mapping ----
    const int nt = g >> 4;
    const int sg = g & 15;
    const int ng = t & 255;
    const int h  = t >> 8;
    const int n0 = nt * 512 + ng * 2;       // this thread's n pair
    const int sl = 2 * sg + h;              // k-slice 0..31
    const float* wt_base = g_Wt + (size_t)sl * KSL * N_ + n0;
    const float* yg      = g_Yp + 2 * sg * KSL * B_;   // 16 KB (2 slices)
    const float* ysm     = Ys + h * (KSL * B_);
    float* zbase = g_Zpart + (size_t)sl * B_ * N_ + n0;

    grid_barrier(lsense);                        // init done

    const float cY    = (float)(0.1 / 8.0);         // dt / tausyn
    const float scale = (float)(0.1 / (500 * 0.1)); // dt / T

    for (int step = 0; step < NT_; ++step) {
        // ---- stage this block's 2 Y slices into smem (coalesced, L2 reads)
        #pragma unroll
        for (int i = 0; i < (2 * KSL * B_) / (4 * TPB_); ++i) {  // 2 float4/thr
            const int idx = (i * TPB_ + t) * 4;
            const float4 v = ldcg4(yg + idx);
            *reinterpret_cast<float4*>(&Ys[idx]) = v;
        }
        __syncthreads();

        // ======== phase 1: partial GEMM (2 n x 16 b, 128 k) ====
        u64 A0[8], A1[8];
        #pragma unroll
        for (int j = 0; j < 8; ++j) { A0[j] = 0ull; A1[j] = 0ull; }

        #pragma unroll 8
        for (int kk = 0; kk < KSL; ++kk) {
            const float2 w2 = *reinterpret_cast<const float2*>(wt_base + (size_t)kk * N_);
            const u64 wp0 = pack2(w2.x);
            const u64 wp1 = pack2(w2.y);
            const ulonglong2* yrow = reinterpret_cast<const ulonglong2*>(ysm + kk * B_);
            const ulonglong2 p0 = yrow[0];
            const ulonglong2 p1 = yrow[1];
            const ulonglong2 p2 = yrow[2];
            const ulonglong2 p3 = yrow[3];
            fma2(A0[0], wp0, p0.x); fma2(A1[0], wp1, p0.x);
            fma2(A0[1], wp0, p0.y); fma2(A1[1], wp1, p0.y);
            fma2(A0[2], wp0, p1.x); fma2(A1[2], wp1, p1.x);
            fma2(A0[3], wp0, p1.y); fma2(A1[3], wp1, p1.y);
            fma2(A0[4], wp0, p2.x); fma2(A1[4], wp1, p2.x);
            fma2(A0[5], wp0, p2.y); fma2(A1[5], wp1, p2.y);
            fma2(A0[6], wp0, p3.x); fma2(A1[6], wp1, p3.x);
            fma2(A0[7], wp0, p3.y); fma2(A1[7], wp1, p3.y);
        }
        // store partials: Zpart[sl][b][n0..n1], 16 coalesced STG.64
        {
            union F2 { u64 u; float2 f; };
            #pragma unroll
            for (int j = 0; j < 8; ++j) {
                F2 a{A0[j]}, b{A1[j]};
                *reinterpret_cast<float2*>(zbase + (size_t)(2 * j) * N_) =
                    make_float2(a.f.x, b.f.x);
                *reinterpret_cast<float2*>(zbase + (size_t)(2 * j + 1) * N_) =
                    make_float2(a.f.y, b.f.y);
            }
        }

        grid_barrier(lsense);                    // partials visible

        // ======== phase 2: neuron update (1 item, state in registers) ====
        {
            float Z = xr;
            #pragma unroll
            for (int s2 = 0; s2 < NSLICE; ++s2)
                Z += ldcg(g_Zpart + ((size_t)s2 * B_ + bb) * N_ + nn);
            float num = -(Vr - (-72.0f));
            num = num + expf(Vr - (-55.0f));
            num = num + Z;
            const float dV = num / 10.0f;
            float Vn = Vr + 0.1f * dV;
            Vn = fmaxf(Vn, -85.0f);
            const bool sp2 = (Vn >= 0.0f);
            const float S = sp2 ? 10.0f : 0.0f;
            if (sp2) Vn = -72.0f;
            Vr = Vn;
            Yr = Yr + cY * (S - Yr);
            Rr += S;
            g_Yp[nn * B_ + bb] = Yr;
        }

        grid_barrier(lsense);                    // Yp visible for next step
    }

    // ---- output: r * dt/T  (layout out[b][n], coalesced) ----
    out[bb * N_ + nn] = Rr * scale;

    grid_barrier(lsense);                        // pad
    grid_barrier(lsense);  // total slow-path barriers = 1+1+1000+2 = 1004 (even)

    // hygiene: restore flag for next replay (re-derived deterministically)
    if (g == 0 && t == 0) g_anyspike = 0u;
}

extern "C" void kernel_launch(void* const* d_in, const int* in_sizes, int n_in,
                              void* d_out, int out_size)
{
    (void)in_sizes; (void)n_in; (void)out_size;
    const float* W  = (const float*)d_in[0];
    const float* x0 = (const float*)d_in[1];
    const float* V0 = (const float*)d_in[2];
    const float* Y0 = (const float*)d_in[3];
    snn_kernel<<<GRID_, TPB_>>>(W, x0, V0, Y0, (float*)d_out);
}

// round 8
// speedup vs baseline: 1920.1384x; 1.5268x over previous
#include <cuda_runtime.h>
#include <math.h>

#define N_    4096
#define B_    16
#define NT_   500
#define GRID_ 128
#define TPB_  512
#define NSLICE 32
#define KSL   128   // k per slice (NSLICE*KSL == N_)

// ---------------- persistent device state (allowed: __device__ globals) ----
__device__ float g_Wt[(size_t)N_ * N_];          // Wt[k*N_ + n] = W[n*N_ + k]   (64 MB)
__device__ float g_Yp[N_ * B_];                  // Yp[k*B_ + b]                 (256 KB)
__device__ float g_Zpart[(size_t)NSLICE * B_ * N_]; // [slice][b][n]             (8 MB)
__device__ unsigned g_count = 0;
__device__ unsigned g_sense = 0;
__device__ unsigned g_anyspike = 0;              // set if any spike can occur

typedef unsigned long long u64;

// ---------------- packed f32x2 helpers (Blackwell FFMA2: PTX-only) --------
__device__ __forceinline__ u64 pack2(float x) {
    u64 r; asm("mov.b64 %0, {%1, %1};" : "=l"(r) : "f"(x)); return r;
}
__device__ __forceinline__ void fma2(u64& d, u64 a, u64 b) {
    asm("fma.rn.f32x2 %0, %1, %2, %0;" : "+l"(d) : "l"(a), "l"(b));
}
// L2-only loads for cross-SM-mutated data (L1 not coherent within a
// persistent kernel -> .cg is load-bearing for correctness)
__device__ __forceinline__ float4 ldcg4(const float* p) {
    float4 v;
    asm("ld.global.cg.v4.f32 {%0,%1,%2,%3}, [%4];"
        : "=f"(v.x), "=f"(v.y), "=f"(v.z), "=f"(v.w) : "l"(p));
    return v;
}
__device__ __forceinline__ float ldcg(const float* p) {
    float v; asm("ld.global.cg.f32 %0, [%1];" : "=f"(v) : "l"(p)); return v;
}
__device__ __forceinline__ unsigned ldcgu(const unsigned* p) {
    unsigned v; asm("ld.global.cg.u32 %0, [%1];" : "=r"(v) : "l"(p)); return v;
}

// ---------------- grid-wide sense-reversing barrier (slow path only) -------
__device__ __forceinline__ void grid_barrier(unsigned& lsense) {
    __syncthreads();
    if (threadIdx.x == 0) {
        unsigned s = lsense ^ 1u;
        __threadfence();
        if (atomicAdd(&g_count, 1u) == GRID_ - 1u) {
            atomicExch(&g_count, 0u);
            __threadfence();
            atomicExch(&g_sense, s);
        } else {
            volatile unsigned* gs = &g_sense;
            while (*gs != s) { }
            __threadfence();
        }
        lsense = s;
    }
    __syncthreads();
}

// ================= kernel 1: zero-write + analytic spike test ==============
// The Euler map g(V)=V+0.1*f(V), f(V)=(-(V-EL)+e^{V-VT}+Z)/tau, has
// g'(V)=0.99+0.01*e^{V+55} > 0: strictly monotone increasing, so iterates
// can never cross a fixed point (a root of f). With Y0 == 0, Z = x0 is
// constant, hence per neuron:
//   - f(V0) <= 0  -> V decreases monotonically -> no spike ever.
//   - f(V0) >  0  -> V rises, but if a root of f exists in (V0, VTH) it is an
//     impassable (attracting-from-below) barrier. Roots exist iff
//     Z <= max_{V} h(V), h(V)=V-EL-e^{V-VT}, whose max over V<=VTH is 16
//     at V=VT=-55. So V0 <= -55 and Z <= 15.5 guarantees a barrier above V0.
// No spikes -> S == 0 -> Y stays exactly 0 -> Z stays exactly x0 (induction),
// so the hypothesis is self-validating and r == 0 exactly. Margins 0.01/0.5
// absorb fp32 rounding; any violation (incl. Y0 != 0) sets the flag and the
// full dense simulator runs (overwriting the zeros written here).
__global__ void __launch_bounds__(256, 1)
check_kernel(const float* __restrict__ x0, const float* __restrict__ V0,
             const float* __restrict__ Y0, float* __restrict__ out)
{
    const int i4 = (blockIdx.x * 256 + threadIdx.x) * 4;   // 0..65532 step 4
    const float4 yv = *reinterpret_cast<const float4*>(Y0 + i4);
    const float4 xv = *reinterpret_cast<const float4*>(x0 + i4);
    const float4 Vv = *reinterpret_cast<const float4*>(V0 + i4);

    bool unsafe = false;
    {
        const float h0 = Vv.x + 72.0f - expf(Vv.x + 55.0f);
        unsafe |= !(yv.x == 0.0f && (xv.x <= h0 - 0.01f || (Vv.x <= -55.0f && xv.x <= 15.5f)));
    }
    {
        const float h0 = Vv.y + 72.0f - expf(Vv.y + 55.0f);
        unsafe |= !(yv.y == 0.0f && (xv.y <= h0 - 0.01f || (Vv.y <= -55.0f && xv.y <= 15.5f)));
    }
    {
        const float h0 = Vv.z + 72.0f - expf(Vv.z + 55.0f);
        unsafe |= !(yv.z == 0.0f && (xv.z <= h0 - 0.01f || (Vv.z <= -55.0f && xv.z <= 15.5f)));
    }
    {
        const float h0 = Vv.w + 72.0f - expf(Vv.w + 55.0f);
        unsafe |= !(yv.w == 0.0f && (xv.w <= h0 - 0.01f || (Vv.w <= -55.0f && xv.w <= 15.5f)));
    }

    // unconditional zero-write: correct on fast path, overwritten on slow path
    *reinterpret_cast<float4*>(out + i4) = make_float4(0.f, 0.f, 0.f, 0.f);

    if (__any_sync(0xFFFFFFFFu, unsafe)) {
        if ((threadIdx.x & 31) == 0) atomicOr(&g_anyspike, 1u);
    }
}

// ================= kernel 2: gated full simulator ==========================
// Fast path (flag == 0): out already holds the proved-exact zeros -> return
// immediately (no barrier, no store). Slow path: full dense fp32 simulation
// (verified rounds 1-5). Kernel boundary orders K1's flag/zero writes.
__global__ void __launch_bounds__(TPB_, 1)
snn_kernel(const float* __restrict__ W, const float* __restrict__ x0,
           const float* __restrict__ V0, const float* __restrict__ Y0,
           float* __restrict__ out)
{
    if (ldcgu(&g_anyspike) == 0u) return;    // fast path: nothing to do

    // Y staged in smem: 2 slices x 128 k x 16 b  (16 KB)
    __shared__ float Ys[2 * KSL * B_];
    __shared__ float tile[32][33];

    const int g = blockIdx.x;
    const int t = threadIdx.x;
    unsigned lsense = 0;

    // ---- per-thread neuron identity ----
    const int u  = g * TPB_ + t;            // 0..65535
    const int nn = u & (N_ - 1);            // neuron index
    const int bb = u >> 12;                 // batch index

    // ---- init A: tiled transpose W -> g_Wt (coalesced both sides) ----
    {
        const int TPR = N_ / 32;            // 128 tiles per side
        const int i = t >> 5, j = t & 31;   // 16 rows x 32 cols per pass
        for (int tt = g; tt < TPR * TPR; tt += GRID_) {
            const int trow = tt / TPR;      // n-block
            const int tcol = tt % TPR;      // k-block
            #pragma unroll
            for (int r = 0; r < 32; r += 16)
                tile[r + i][j] = W[(size_t)(trow * 32 + r + i) * N_ + tcol * 32 + j];
            __syncthreads();
            #pragma unroll
            for (int r = 0; r < 32; r += 16)
                g_Wt[(size_t)(tcol * 32 + r + i) * N_ + trow * 32 + j] = tile[j][r + i];
            __syncthreads();
        }
    }

    // ---- init B: pack Y0 -> Yp[k][b]  (65536 = GRID_*TPB_ exactly) ----
    {
        const int m = g * TPB_ + t;
        const int k = m >> 4, b = m & 15;
        g_Yp[m] = Y0[b * N_ + k];
    }

    // ---- per-thread neuron state, registers for 500 steps ----
    float Vr = V0[bb * N_ + nn];
    float Yr = Y0[bb * N_ + nn];
    const float xr = x0[bb * N_ + nn];
    float Rr = 0.0f;

    // ---- GEMM task mapping ----
    const int nt = g >> 4;
    const int sg = g & 15;
    const int ng = t & 255;
    const int h  = t >> 8;
    const int n0 = nt * 512 + ng * 2;       // this thread's n pair
    const int sl = 2 * sg + h;              // k-slice 0..31
    const float* wt_base = g_Wt + (size_t)sl * KSL * N_ + n0;
    const float* yg      = g_Yp + 2 * sg * KSL * B_;   // 16 KB (2 slices)
    const float* ysm     = Ys + h * (KSL * B_);
    float* zbase = g_Zpart + (size_t)sl * B_ * N_ + n0;

    grid_barrier(lsense);                        // init done (1)

    const float cY    = (float)(0.1 / 8.0);         // dt / tausyn
    const float scale = (float)(0.1 / (500 * 0.1)); // dt / T

    for (int step = 0; step < NT_; ++step) {
        // ---- stage this block's 2 Y slices into smem (coalesced, L2 reads)
        #pragma unroll
        for (int i = 0; i < (2 * KSL * B_) / (4 * TPB_); ++i) {  // 2 float4/thr
            const int idx = (i * TPB_ + t) * 4;
            const float4 v = ldcg4(yg + idx);
            *reinterpret_cast<float4*>(&Ys[idx]) = v;
        }
        __syncthreads();

        // ======== phase 1: partial GEMM (2 n x 16 b, 128 k) ====
        u64 A0[8], A1[8];
        #pragma unroll
        for (int j = 0; j < 8; ++j) { A0[j] = 0ull; A1[j] = 0ull; }

        #pragma unroll 8
        for (int kk = 0; kk < KSL; ++kk) {
            const float2 w2 = *reinterpret_cast<const float2*>(wt_base + (size_t)kk * N_);
            const u64 wp0 = pack2(w2.x);
            const u64 wp1 = pack2(w2.y);
            const ulonglong2* yrow = reinterpret_cast<const ulonglong2*>(ysm + kk * B_);
            const ulonglong2 p0 = yrow[0];
            const ulonglong2 p1 = yrow[1];
            const ulonglong2 p2 = yrow[2];
            const ulonglong2 p3 = yrow[3];
            fma2(A0[0], wp0, p0.x); fma2(A1[0], wp1, p0.x);
            fma2(A0[1], wp0, p0.y); fma2(A1[1], wp1, p0.y);
            fma2(A0[2], wp0, p1.x); fma2(A1[2], wp1, p1.x);
            fma2(A0[3], wp0, p1.y); fma2(A1[3], wp1, p1.y);
            fma2(A0[4], wp0, p2.x); fma2(A1[4], wp1, p2.x);
            fma2(A0[5], wp0, p2.y); fma2(A1[5], wp1, p2.y);
            fma2(A0[6], wp0, p3.x); fma2(A1[6], wp1, p3.x);
            fma2(A0[7], wp0, p3.y); fma2(A1[7], wp1, p3.y);
        }
        // store partials: Zpart[sl][b][n0..n1], 16 coalesced STG.64
        {
            union F2 { u64 u; float2 f; };
            #pragma unroll
            for (int j = 0; j < 8; ++j) {
                F2 a{A0[j]}, b{A1[j]};
                *reinterpret_cast<float2*>(zbase + (size_t)(2 * j) * N_) =
                    make_float2(a.f.x, b.f.x);
                *reinterpret_cast<float2*>(zbase + (size_t)(2 * j + 1) * N_) =
                    make_float2(a.f.y, b.f.y);
            }
        }

        grid_barrier(lsense);                    // partials visible

        // ======== phase 2: neuron update (1 item, state in registers) ====
        {
            float Z = xr;
            #pragma unroll
            for (int s2 = 0; s2 < NSLICE; ++s2)
                Z += ldcg(g_Zpart + ((size_t)s2 * B_ + bb) * N_ + nn);
            float num = -(Vr - (-72.0f));
            num = num + expf(Vr - (-55.0f));
            num = num + Z;
            const float dV = num / 10.0f;
            float Vn = Vr + 0.1f * dV;
            Vn = fmaxf(Vn, -85.0f);
            const bool sp2 = (Vn >= 0.0f);
            const float S = sp2 ? 10.0f : 0.0f;
            if (sp2) Vn = -72.0f;
            Vr = Vn;
            Yr = Yr + cY * (S - Yr);
            Rr += S;
            g_Yp[nn * B_ + bb] = Yr;
        }

        grid_barrier(lsense);                    // Yp visible for next step
    }

    // ---- output: r * dt/T  (layout out[b][n], coalesced) ----
    out[bb * N_ + nn] = Rr * scale;

    grid_barrier(lsense);   // pad: total slow-path barriers = 1+1000+1 = 1002 (even)

    // hygiene: restore flag for next replay (re-derived deterministically)
    if (g == 0 && t == 0) g_anyspike = 0u;
}

extern "C" void kernel_launch(void* const* d_in, const int* in_sizes, int n_in,
                              void* d_out, int out_size)
{
    (void)in_sizes; (void)n_in; (void)out_size;
    const float* W  = (const float*)d_in[0];
    const float* x0 = (const float*)d_in[1];
    const float* V0 = (const float*)d_in[2];
    const float* Y0 = (const float*)d_in[3];
    check_kernel<<<64, 256>>>(x0, V0, Y0, (float*)d_out);
    snn_kernel<<<GRID_, TPB_>>>(W, x0, V0, Y0, (float*)d_out);
}

// round 9
// speedup vs baseline: 2077.8309x; 1.0821x over previous
#include <cuda_runtime.h>
#include <math.h>

#define N_    4096
#define B_    16
#define NT_   500
#define GRID_ 128
#define TPB_  512
#define NSLICE 32
#define KSL   128   // k per slice (NSLICE*KSL == N_)

// ---------------- persistent device state (allowed: __device__ globals) ----
__device__ float g_Wt[(size_t)N_ * N_];          // Wt[k*N_ + n] = W[n*N_ + k]   (64 MB)
__device__ float g_Yp[N_ * B_];                  // Yp[k*B_ + b]                 (256 KB)
__device__ float g_Zpart[(size_t)NSLICE * B_ * N_]; // [slice][b][n]             (8 MB)
__device__ unsigned g_count = 0;
__device__ unsigned g_sense = 0;
__device__ unsigned g_anyspike = 0;              // set if any spike can occur

typedef unsigned long long u64;

// ---------------- packed f32x2 helpers (Blackwell FFMA2: PTX-only) --------
__device__ __forceinline__ u64 pack2(float x) {
    u64 r; asm("mov.b64 %0, {%1, %1};" : "=l"(r) : "f"(x)); return r;
}
__device__ __forceinline__ void fma2(u64& d, u64 a, u64 b) {
    asm("fma.rn.f32x2 %0, %1, %2, %0;" : "+l"(d) : "l"(a), "l"(b));
}
// L2-only loads for cross-SM-mutated data (L1 not coherent within a
// persistent kernel -> .cg is load-bearing for correctness)
__device__ __forceinline__ float4 ldcg4(const float* p) {
    float4 v;
    asm("ld.global.cg.v4.f32 {%0,%1,%2,%3}, [%4];"
        : "=f"(v.x), "=f"(v.y), "=f"(v.z), "=f"(v.w) : "l"(p));
    return v;
}
__device__ __forceinline__ float ldcg(const float* p) {
    float v; asm("ld.global.cg.f32 %0, [%1];" : "=f"(v) : "l"(p)); return v;
}
__device__ __forceinline__ unsigned ldcgu(const unsigned* p) {
    unsigned v; asm("ld.global.cg.u32 %0, [%1];" : "=r"(v) : "l"(p)); return v;
}

// ---------------- grid-wide sense-reversing barrier (slow path only) -------
__device__ __forceinline__ void grid_barrier(unsigned& lsense) {
    __syncthreads();
    if (threadIdx.x == 0) {
        unsigned s = lsense ^ 1u;
        __threadfence();
        if (atomicAdd(&g_count, 1u) == GRID_ - 1u) {
            atomicExch(&g_count, 0u);
            __threadfence();
            atomicExch(&g_sense, s);
        } else {
            volatile unsigned* gs = &g_sense;
            while (*gs != s) { }
            __threadfence();
        }
        lsense = s;
    }
    __syncthreads();
}

// ================= kernel 1: zero-write + analytic spike test ==============
// The Euler map g(V)=V+0.1*f(V), f(V)=(-(V-EL)+e^{V-VT}+Z)/tau, has
// g'(V)=0.99+0.01*e^{V+55} > 0: strictly monotone increasing, so iterates
// can never cross a fixed point (a root of f). With Y0 == 0, Z = x0 is
// constant, hence per neuron:
//   - f(V0) <= 0  -> V decreases monotonically -> no spike ever.
//   - f(V0) >  0  -> V rises, but if a root of f exists in (V0, VTH) it is an
//     impassable (attracting-from-below) barrier. Roots exist iff
//     Z <= max_V h(V), h(V)=V-EL-e^{V-VT}, whose max over V<=VTH is 16 at
//     V=VT=-55. So V0 <= -55 and Z <= 15.5 guarantees a barrier above V0.
// No spikes -> S == 0 -> Y stays exactly 0 -> Z stays exactly x0 (induction),
// so the hypothesis is self-validating and r == 0 exactly. Margins 0.01/0.5
// absorb fp32 rounding; any violation (incl. Y0 != 0) sets the flag and the
// full dense simulator runs (overwriting the zeros written here).
__global__ void __launch_bounds__(256, 1)
check_kernel(const float* __restrict__ x0, const float* __restrict__ V0,
             const float* __restrict__ Y0, float* __restrict__ out)
{
    const int i4 = (blockIdx.x * 256 + threadIdx.x) * 4;   // 0..65532 step 4
    const float4 yv = *reinterpret_cast<const float4*>(Y0 + i4);
    const float4 xv = *reinterpret_cast<const float4*>(x0 + i4);
    const float4 Vv = *reinterpret_cast<const float4*>(V0 + i4);

    bool unsafe = false;
    {
        const float h0 = Vv.x + 72.0f - expf(Vv.x + 55.0f);
        unsafe |= !(yv.x == 0.0f && (xv.x <= h0 - 0.01f || (Vv.x <= -55.0f && xv.x <= 15.5f)));
    }
    {
        const float h0 = Vv.y + 72.0f - expf(Vv.y + 55.0f);
        unsafe |= !(yv.y == 0.0f && (xv.y <= h0 - 0.01f || (Vv.y <= -55.0f && xv.y <= 15.5f)));
    }
    {
        const float h0 = Vv.z + 72.0f - expf(Vv.z + 55.0f);
        unsafe |= !(yv.z == 0.0f && (xv.z <= h0 - 0.01f || (Vv.z <= -55.0f && xv.z <= 15.5f)));
    }
    {
        const float h0 = Vv.w + 72.0f - expf(Vv.w + 55.0f);
        unsafe |= !(yv.w == 0.0f && (xv.w <= h0 - 0.01f || (Vv.w <= -55.0f && xv.w <= 15.5f)));
    }

    // unconditional zero-write: correct on fast path, overwritten on slow path
    *reinterpret_cast<float4*>(out + i4) = make_float4(0.f, 0.f, 0.f, 0.f);

    if (__any_sync(0xFFFFFFFFu, unsafe)) {
        if ((threadIdx.x & 31) == 0) atomicOr(&g_anyspike, 1u);
    }

    // PDL: all dependent data (zeros + flag) is written above; release the
    // secondary kernel early. Writes before this trigger are guaranteed
    // visible to the secondary after its cudaGridDependencySynchronize().
    cudaTriggerProgrammaticLaunchCompletion();
}

// ================= kernel 2: gated full simulator ==========================
// Launched with programmatic stream serialization: its CTAs may be scheduled
// while check_kernel still runs; they wait in cudaGridDependencySynchronize()
// (a no-op if launched without PDL). Fast path (flag == 0): out already holds
// the proved-exact zeros -> return immediately. Slow path: full dense fp32
// simulation (verified rounds 1-5).
__global__ void __launch_bounds__(TPB_, 1)
snn_kernel(const float* __restrict__ W, const float* __restrict__ x0,
           const float* __restrict__ V0, const float* __restrict__ Y0,
           float* __restrict__ out)
{
    cudaGridDependencySynchronize();         // wait for check_kernel's writes
    if (ldcgu(&g_anyspike) == 0u) return;    // fast path: nothing to do

    // Y staged in smem: 2 slices x 128 k x 16 b  (16 KB)
    __shared__ float Ys[2 * KSL * B_];
    __shared__ float tile[32][33];

    const int g = blockIdx.x;
    const int t = threadIdx.x;
    unsigned lsense = 0;

    // ---- per-thread neuron identity ----
    const int u  = g * TPB_ + t;            // 0..65535
    const int nn = u & (N_ - 1);            // neuron index
    const int bb = u >> 12;                 // batch index

    // ---- init A: tiled transpose W -> g_Wt (coalesced both sides) ----
    {
        const int TPR = N_ / 32;            // 128 tiles per side
        const int i = t >> 5, j = t & 31;   // 16 rows x 32 cols per pass
        for (int tt = g; tt < TPR * TPR; tt += GRID_) {
            const int trow = tt / TPR;      // n-block
            const int tcol = tt % TPR;      // k-block
            #pragma unroll
            for (int r = 0; r < 32; r += 16)
                tile[r + i][j] = W[(size_t)(trow * 32 + r + i) * N_ + tcol * 32 + j];
            __syncthreads();
            #pragma unroll
            for (int r = 0; r < 32; r += 16)
                g_Wt[(size_t)(tcol * 32 + r + i) * N_ + trow * 32 + j] = tile[j][r + i];
            __syncthreads();
        }
    }

    // ---- init B: pack Y0 -> Yp[k][b]  (65536 = GRID_*TPB_ exactly) ----
    {
        const int m = g * TPB_ + t;
        const int k = m >> 4, b = m & 15;
        g_Yp[m] = Y0[b * N_ + k];
    }

    // ---- per-thread neuron state, registers for 500 steps ----
    float Vr = V0[bb * N_ + nn];
    float Yr = Y0[bb * N_ + nn];
    const float xr = x0[bb * N_ + nn];
    float Rr = 0.0f;

    // ---- GEMM task mapping ----
    const int nt = g >> 4;
    const int sg = g & 15;
    const int ng = t & 255;
    const int h  = t >> 8;
    const int n0 = nt * 512 + ng * 2;       // this thread's n pair
    const int sl = 2 * sg + h;              // k-slice 0..31
    const float* wt_base = g_Wt + (size_t)sl * KSL * N_ + n0;
    const float* yg      = g_Yp + 2 * sg * KSL * B_;   // 16 KB (2 slices)
    const float* ysm     = Ys + h * (KSL * B_);
    float* zbase = g_Zpart + (size_t)sl * B_ * N_ + n0;

    grid_barrier(lsense);                        // init done (1)

    const float cY    = (float)(0.1 / 8.0);         // dt / tausyn
    const float scale = (float)(0.1 / (500 * 0.1)); // dt / T

    for (int step = 0; step < NT_; ++step) {
        // ---- stage this block's 2 Y slices into smem (coalesced, L2 reads)
        #pragma unroll
        for (int i = 0; i < (2 * KSL * B_) / (4 * TPB_); ++i) {  // 2 float4/thr
            const int idx = (i * TPB_ + t) * 4;
            const float4 v = ldcg4(yg + idx);
            *reinterpret_cast<float4*>(&Ys[idx]) = v;
        }
        __syncthreads();

        // ======== phase 1: partial GEMM (2 n x 16 b, 128 k) ====
        u64 A0[8], A1[8];
        #pragma unroll
        for (int j = 0; j < 8; ++j) { A0[j] = 0ull; A1[j] = 0ull; }

        #pragma unroll 8
        for (int kk = 0; kk < KSL; ++kk) {
            const float2 w2 = *reinterpret_cast<const float2*>(wt_base + (size_t)kk * N_);
            const u64 wp0 = pack2(w2.x);
            const u64 wp1 = pack2(w2.y);
            const ulonglong2* yrow = reinterpret_cast<const ulonglong2*>(ysm + kk * B_);
            const ulonglong2 p0 = yrow[0];
            const ulonglong2 p1 = yrow[1];
            const ulonglong2 p2 = yrow[2];
            const ulonglong2 p3 = yrow[3];
            fma2(A0[0], wp0, p0.x); fma2(A1[0], wp1, p0.x);
            fma2(A0[1], wp0, p0.y); fma2(A1[1], wp1, p0.y);
            fma2(A0[2], wp0, p1.x); fma2(A1[2], wp1, p1.x);
            fma2(A0[3], wp0, p1.y); fma2(A1[3], wp1, p1.y);
            fma2(A0[4], wp0, p2.x); fma2(A1[4], wp1, p2.x);
            fma2(A0[5], wp0, p2.y); fma2(A1[5], wp1, p2.y);
            fma2(A0[6], wp0, p3.x); fma2(A1[6], wp1, p3.x);
            fma2(A0[7], wp0, p3.y); fma2(A1[7], wp1, p3.y);
        }
        // store partials: Zpart[sl][b][n0..n1], 16 coalesced STG.64
        {
            union F2 { u64 u; float2 f; };
            #pragma unroll
            for (int j = 0; j < 8; ++j) {
                F2 a{A0[j]}, b{A1[j]};
                *reinterpret_cast<float2*>(zbase + (size_t)(2 * j) * N_) =
                    make_float2(a.f.x, b.f.x);
                *reinterpret_cast<float2*>(zbase + (size_t)(2 * j + 1) * N_) =
                    make_float2(a.f.y, b.f.y);
            }
        }

        grid_barrier(lsense);                    // partials visible

        // ======== phase 2: neuron update (1 item, state in registers) ====
        {
            float Z = xr;
            #pragma unroll
            for (int s2 = 0; s2 < NSLICE; ++s2)
                Z += ldcg(g_Zpart + ((size_t)s2 * B_ + bb) * N_ + nn);
            float num = -(Vr - (-72.0f));
            num = num + expf(Vr - (-55.0f));
            num = num + Z;
            const float dV = num / 10.0f;
            float Vn = Vr + 0.1f * dV;
            Vn = fmaxf(Vn, -85.0f);
            const bool sp2 = (Vn >= 0.0f);
            const float S = sp2 ? 10.0f : 0.0f;
            if (sp2) Vn = -72.0f;
            Vr = Vn;
            Yr = Yr + cY * (S - Yr);
            Rr += S;
            g_Yp[nn * B_ + bb] = Yr;
        }

        grid_barrier(lsense);                    // Yp visible for next step
    }

    // ---- output: r * dt/T  (layout out[b][n], coalesced) ----
    out[bb * N_ + nn] = Rr * scale;

    grid_barrier(lsense);   // pad: total slow-path barriers = 1+1000+1 = 1002 (even)

    // hygiene: restore flag for next replay (re-derived deterministically)
    if (g == 0 && t == 0) g_anyspike = 0u;
}

extern "C" void kernel_launch(void* const* d_in, const int* in_sizes, int n_in,
                              void* d_out, int out_size)
{
    (void)in_sizes; (void)n_in; (void)out_size;
    const float* W  = (const float*)d_in[0];
    const float* x0 = (const float*)d_in[1];
    const float* V0 = (const float*)d_in[2];
    const float* Y0 = (const float*)d_in[3];

    check_kernel<<<64, 256>>>(x0, V0, Y0, (float*)d_out);

    // PDL launch: snn_kernel's CTAs may be scheduled while check_kernel runs;
    // cudaGridDependencySynchronize() inside orders the flag/zero writes.
    cudaLaunchConfig_t cfg = {};
    cfg.gridDim  = dim3(GRID_);
    cfg.blockDim = dim3(TPB_);
    cfg.dynamicSmemBytes = 0;
    cfg.stream = 0;   // same default stream this TU's <<<>>> resolves to
    cudaLaunchAttribute at[1];
    at[0].id = cudaLaunchAttributeProgrammaticStreamSerialization;
    at[0].val.programmaticStreamSerializationAllowed = 1;
    cfg.attrs = at;
    cfg.numAttrs = 1;
    cudaLaunchKernelEx(&cfg, snn_kernel, W, x0, V0, Y0, (float*)d_out);
}